// round 2
// baseline (speedup 1.0000x reference)
#include <cuda_runtime.h>

// ---------------- problem constants (fixed instance) ----------------
#define WIN   12
#define GRP   128
#define MAXN  87                   // ceil(1024/12)+1
#define MWP   (MAXN*MAXN)          // 7569
#define CKR   (4*MWP*WIN*WIN)      // 4*7569*144 = 4359744  (key range per axis, B=4)
#define NBITS (2*CKR)              // 8719488 bits (x keys then y keys)
#define NW    (NBITS/32)           // 272484 words
#define WORDS_PER_BLOCK 4096       // 256 thr * 16 words
#define NSB   67                   // ceil(NW / 4096)
#define NW_PAD (NSB*WORDS_PER_BLOCK) // 274432 (tail words stay zero)
#define NMAX  1000448

// ---------------- scratch (no allocation allowed) ----------------
__device__ unsigned g_mask[NW_PAD];   // presence bits
__device__ int      g_wpref[NW_PAD];  // per-word exclusive popcount prefix (block-local)
__device__ int      g_bsum[NSB];      // per-scan-block totals -> scanned offsets
__device__ int      g_keyx[NMAX];
__device__ int      g_keyy[NMAX];
__device__ int      g_permx[NMAX];    // int copy of perm_x for the gather

// ---------------- helpers ----------------
__device__ __forceinline__ int blockScanExcl256(int val, int& blockTotal) {
    const unsigned FULL = 0xffffffffu;
    int lane = threadIdx.x & 31, wid = threadIdx.x >> 5;
    int inc = val;
#pragma unroll
    for (int o = 1; o < 32; o <<= 1) {
        int t = __shfl_up_sync(FULL, inc, o);
        if (lane >= o) inc += t;
    }
    __shared__ int warpSum[8];
    __shared__ int warpOff[8];
    __shared__ int totS;
    if (lane == 31) warpSum[wid] = inc;
    __syncthreads();
    if (threadIdx.x < 8) {
        int w  = warpSum[threadIdx.x];
        int wi = w;
#pragma unroll
        for (int o = 1; o < 8; o <<= 1) {
            int t = __shfl_up_sync(0xffu, wi, o);
            if ((int)threadIdx.x >= o) wi += t;
        }
        warpOff[threadIdx.x] = wi - w;
        if (threadIdx.x == 7) totS = wi;
    }
    __syncthreads();
    blockTotal = totS;
    return warpOff[wid] + (inc - val);
}

// ---------------- kernels ----------------
__global__ void k_zero() {
    uint4 z = make_uint4(0, 0, 0, 0);
    int total  = NW_PAD / 4;
    int stride = gridDim.x * blockDim.x;
    for (int i = blockIdx.x * blockDim.x + threadIdx.x; i < total; i += stride)
        ((uint4*)g_mask)[i] = z;
}

// keys + presence bits + win2flat output
__global__ void k_build(const int* __restrict__ coords, float* __restrict__ out,
                        int n, int nper, int biasStep, int P) {
    int i = blockIdx.x * blockDim.x + threadIdx.x;
    if (i >= n) return;
    int b = coords[3 * i + 0];
    int y = coords[3 * i + 1];
    int x = coords[3 * i + 2];
    int wx = x / WIN, cx = x - wx * WIN;
    int wy = y / WIN, cy = y - wy * WIN;
    int vx = (b * MWP + wx * MAXN + wy) * (WIN * WIN) + cx * WIN + cy;
    int vy = (b * MWP + wy * MAXN + wx) * (WIN * WIN) + cy * WIN + cx;
    g_keyx[i] = vx;
    g_keyy[i] = vy;
    atomicOr(&g_mask[vx >> 5],          1u << (vx & 31));
    int vyb = CKR + vy;
    atomicOr(&g_mask[vyb >> 5],         1u << (vyb & 31));
    int bb = i / nper;
    out[P + i] = (float)(i + bb * biasStep);   // win2flat
}

// pass 1: per-word popcount exclusive prefix (block-local) + block totals
__global__ void k_scan1() {
    int base = blockIdx.x * WORDS_PER_BLOCK + threadIdx.x * 16;
    unsigned w[16];
#pragma unroll
    for (int q = 0; q < 4; q++) {
        uint4 a = *((const uint4*)(g_mask + base + q * 4));
        w[q * 4 + 0] = a.x; w[q * 4 + 1] = a.y;
        w[q * 4 + 2] = a.z; w[q * 4 + 3] = a.w;
    }
    int pre[16];
    int sum = 0;
#pragma unroll
    for (int k = 0; k < 16; k++) { pre[k] = sum; sum += __popc(w[k]); }
    int tot;
    int ex = blockScanExcl256(sum, tot);
#pragma unroll
    for (int q = 0; q < 4; q++) {
        int4 a;
        a.x = pre[q * 4 + 0] + ex; a.y = pre[q * 4 + 1] + ex;
        a.z = pre[q * 4 + 2] + ex; a.w = pre[q * 4 + 3] + ex;
        *((int4*)(g_wpref + base + q * 4)) = a;
    }
    if (threadIdx.x == 0) g_bsum[blockIdx.x] = tot;
}

// pass 2: exclusive scan of the 67 block totals (single block)
__global__ void k_scan2() {
    int idx = threadIdx.x;
    int val = (idx < NSB) ? g_bsum[idx] : 0;
    int tot;
    int ex = blockScanExcl256(val, tot);
    if (idx < NSB) g_bsum[idx] = ex;
}

// ranks -> perm_x / perm_y
__global__ void k_scatter(float* __restrict__ out, int n, int P) {
    int i = blockIdx.x * blockDim.x + threadIdx.x;
    if (i >= n) return;
    int kx  = g_keyx[i];
    int kyb = CKR + g_keyy[i];
    int wx = kx >> 5,  bx = kx & 31;
    int wy = kyb >> 5, by = kyb & 31;
    unsigned mx = g_mask[wx], my = g_mask[wy];
    int rx = g_wpref[wx] + g_bsum[wx >> 12] + __popc(mx & ((1u << bx) - 1u));
    int ry = g_wpref[wy] + g_bsum[wy >> 12] + __popc(my & ((1u << by) - 1u)) - n;
    g_permx[rx] = i;
    out[(size_t)P + n + rx]     = (float)i;   // perm_x
    out[(size_t)P + 2 * n + ry] = (float)i;   // perm_y
}

// flat2win output + padded gather: 1 row per warp, 32 lanes x float4 = 512B
__global__ void k_gather(const float* __restrict__ feats, float* __restrict__ out,
                         int n, int P, int nper, int nump, int biasStep) {
    int row = blockIdx.x * 8 + (threadIdx.x >> 5);
    if (row >= P) return;
    int lane = threadIdx.x & 31;
    int pb   = row / nump;
    int off  = row - pb * nump;
    int bias = pb * biasStep;
    int f2w  = (off >= nper) ? (row - GRP - bias) : (row - bias);
    if (lane == 0) out[row] = (float)f2w;     // flat2win
    int src = g_permx[f2w];
    const float4* s = (const float4*)(feats + (size_t)src * 128);
    float4*       d = (float4*)(out + (size_t)P + (size_t)3 * n + (size_t)row * 128);
    d[lane] = s[lane];
}

// ---------------- launch ----------------
extern "C" void kernel_launch(void* const* d_in, const int* in_sizes, int n_in,
                              void* d_out, int out_size) {
    const int*   coords = (const int*)d_in[0];
    const float* feats  = (const float*)d_in[1];
    float*       out    = (float*)d_out;

    int n = in_sizes[0] / 3;                               // 999964
    long long Pll = ((long long)out_size - 3LL * n) / 129; // 1000448
    int P = (int)Pll;
    int nper = n / 4;
    int nump = P / 4;
    int biasStep = nump - nper;                            // 121

    k_zero   <<<256, 256>>>();
    k_build  <<<(n + 255) / 256, 256>>>(coords, out, n, nper, biasStep, P);
    k_scan1  <<<NSB, 256>>>();
    k_scan2  <<<1, 256>>>();
    k_scatter<<<(n + 255) / 256, 256>>>(out, n, P);
    k_gather <<<(P + 7) / 8, 256>>>(feats, out, n, P, nper, nump, biasStep);
}

// round 17
// speedup vs baseline: 1.2925x; 1.2925x over previous
#include <cuda_runtime.h>

// ---------------- problem constants (fixed instance) ----------------
#define WIN   12
#define GRP   128
#define MAXN  87                   // ceil(1024/12)+1
#define MWP   (MAXN*MAXN)          // 7569
#define CKR   (4*MWP*WIN*WIN)      // 4*7569*144 = 4359744  (key range per axis, B=4)
#define NBITS (2*CKR)              // 8719488 bits (x keys then y keys)
#define NW    (NBITS/32)           // 272484 words
#define WORDS_PER_BLOCK 4096       // 256 thr * 16 words
#define NSB   67                   // ceil(NW / 4096)
#define NW_PAD (NSB*WORDS_PER_BLOCK) // 274432 (tail words stay zero)

// ---------------- scratch (no allocation allowed) ----------------
// interleaved {mask, excl-prefix} per 32-key word: one LDG.64 gets both
__device__ uint2 g_mw[NW_PAD];
__device__ int   g_bsum[NSB];      // per-scan-block totals (unscanned)

// ---------------- helpers ----------------
__device__ __forceinline__ int blockScanExcl256(int val, int& blockTotal) {
    const unsigned FULL = 0xffffffffu;
    int lane = threadIdx.x & 31, wid = threadIdx.x >> 5;
    int inc = val;
#pragma unroll
    for (int o = 1; o < 32; o <<= 1) {
        int t = __shfl_up_sync(FULL, inc, o);
        if (lane >= o) inc += t;
    }
    __shared__ int warpSum[8];
    __shared__ int warpOff[8];
    __shared__ int totS;
    if (lane == 31) warpSum[wid] = inc;
    __syncthreads();
    if (threadIdx.x < 8) {
        int w  = warpSum[threadIdx.x];
        int wi = w;
#pragma unroll
        for (int o = 1; o < 8; o <<= 1) {
            int t = __shfl_up_sync(0xffu, wi, o);
            if ((int)threadIdx.x >= o) wi += t;
        }
        warpOff[threadIdx.x] = wi - w;
        if (threadIdx.x == 7) totS = wi;
    }
    __syncthreads();
    blockTotal = totS;
    return warpOff[wid] + (inc - val);
}

__device__ __forceinline__ void keys_from_coord(int b, int y, int x, int& vx, int& vy) {
    int wx = x / WIN, cx = x - wx * WIN;
    int wy = y / WIN, cy = y - wy * WIN;
    vx = (b * MWP + wx * MAXN + wy) * (WIN * WIN) + cx * WIN + cy;
    vy = (b * MWP + wy * MAXN + wx) * (WIN * WIN) + cy * WIN + cx;
}

// ---------------- kernels ----------------
__global__ void k_zero() {
    uint4 z = make_uint4(0, 0, 0, 0);
    int total  = NW_PAD / 2;           // uint4 = 2 uint2
    int stride = gridDim.x * blockDim.x;
    for (int i = blockIdx.x * blockDim.x + threadIdx.x; i < total; i += stride)
        ((uint4*)g_mw)[i] = z;
}

// presence bits + win2flat output
__global__ void k_build(const int* __restrict__ coords, float* __restrict__ out,
                        int n, int nper, int biasStep, int P) {
    int i = blockIdx.x * blockDim.x + threadIdx.x;
    if (i >= n) return;
    int b = coords[3 * i + 0];
    int y = coords[3 * i + 1];
    int x = coords[3 * i + 2];
    int vx, vy;
    keys_from_coord(b, y, x, vx, vy);
    atomicOr(&g_mw[vx >> 5].x, 1u << (vx & 31));
    int vyb = CKR + vy;
    atomicOr(&g_mw[vyb >> 5].x, 1u << (vyb & 31));
    int bb = i / nper;
    out[P + i] = (float)(i + bb * biasStep);   // win2flat
}

// per-word popcount exclusive prefix (block-local) + block totals
__global__ void k_scan1() {
    int base = blockIdx.x * WORDS_PER_BLOCK + threadIdx.x * 16;  // word index
    unsigned m[16];
#pragma unroll
    for (int q = 0; q < 8; q++) {                // uint4 = 2 words {m,p,m,p}
        uint4 a = *((const uint4*)(g_mw + base) + q);
        m[q * 2 + 0] = a.x;
        m[q * 2 + 1] = a.z;
    }
    int pre[16];
    int sum = 0;
#pragma unroll
    for (int k = 0; k < 16; k++) { pre[k] = sum; sum += __popc(m[k]); }
    int tot;
    int ex = blockScanExcl256(sum, tot);
#pragma unroll
    for (int q = 0; q < 8; q++) {
        uint4 a;
        a.x = m[q * 2 + 0]; a.y = (unsigned)(pre[q * 2 + 0] + ex);
        a.z = m[q * 2 + 1]; a.w = (unsigned)(pre[q * 2 + 1] + ex);
        *((uint4*)(g_mw + base) + q) = a;
    }
    if (threadIdx.x == 0) g_bsum[blockIdx.x] = tot;
}

// ranks -> perm_x / perm_y. The 67-entry block-total scan is recomputed
// per block in shared memory (cheap; removes a dedicated launch).
__global__ void k_scatter(const int* __restrict__ coords, float* __restrict__ out,
                          int n, int P) {
    __shared__ int sOff[NSB];
    {
        int idx = threadIdx.x;
        int val = (idx < NSB) ? g_bsum[idx] : 0;
        int tot;
        int ex = blockScanExcl256(val, tot);
        if (idx < NSB) sOff[idx] = ex;
        __syncthreads();
    }
    int i = blockIdx.x * blockDim.x + threadIdx.x;
    if (i >= n) return;
    int b = coords[3 * i + 0];
    int y = coords[3 * i + 1];
    int x = coords[3 * i + 2];
    int vx, vy;
    keys_from_coord(b, y, x, vx, vy);
    int kyb = CKR + vy;
    int wx = vx >> 5,  bx = vx & 31;
    int wy = kyb >> 5, by = kyb & 31;
    uint2 ax = g_mw[wx];
    uint2 ay = g_mw[wy];
    int rx = (int)ax.y + sOff[wx >> 12] + __popc(ax.x & ((1u << bx) - 1u));
    int ry = (int)ay.y + sOff[wy >> 12] + __popc(ay.x & ((1u << by) - 1u)) - n;
    __stcs(&out[(size_t)P + n + rx],     (float)i);   // perm_x
    __stcs(&out[(size_t)P + 2 * n + ry], (float)i);   // perm_y
}

// flat2win output + padded gather: 4 rows per warp (MLP=4 random rows in
// flight per lane before any store). 8 warps * 4 rows = 32 rows per block.
// P = 1000448 is divisible by 32 -> no tail path.
__global__ void k_gather(const float* __restrict__ feats, float* __restrict__ out,
                         int n, int P, int nper, int nump, int biasStep) {
    int rowBase = blockIdx.x * 32 + (threadIdx.x >> 5) * 4;
    int lane = threadIdx.x & 31;
    const float* permx = out + (size_t)P + n;
    float* pad = out + (size_t)P + (size_t)3 * n;

    int f2w[4];
    int src[4];
#pragma unroll
    for (int r = 0; r < 4; r++) {
        int row  = rowBase + r;
        int pb   = row / nump;
        int off  = row - pb * nump;
        int bias = pb * biasStep;
        f2w[r] = (off >= nper) ? (row - GRP - bias) : (row - bias);
    }
#pragma unroll
    for (int r = 0; r < 4; r++)
        src[r] = (int)__ldg(&permx[f2w[r]]);   // exact int < 2^24, warp-broadcast

    float4 v[4];
#pragma unroll
    for (int r = 0; r < 4; r++) {              // all 4 random row loads in flight
        const float4* s = (const float4*)(feats + (size_t)src[r] * 128);
        v[r] = __ldcs(s + lane);
    }
    // flat2win: statically-indexed predicated stores (keeps f2w in registers;
    // a lane-indexed f2w[lane] would demote the array to local memory and
    // break the front-batched LDG pattern above)
    if (lane == 0) out[rowBase + 0] = (float)f2w[0];
    if (lane == 1) out[rowBase + 1] = (float)f2w[1];
    if (lane == 2) out[rowBase + 2] = (float)f2w[2];
    if (lane == 3) out[rowBase + 3] = (float)f2w[3];
#pragma unroll
    for (int r = 0; r < 4; r++)
        __stcs((float4*)(pad + (size_t)(rowBase + r) * 128) + lane, v[r]);
}

// ---------------- launch ----------------
extern "C" void kernel_launch(void* const* d_in, const int* in_sizes, int n_in,
                              void* d_out, int out_size) {
    const int*   coords = (const int*)d_in[0];
    const float* feats  = (const float*)d_in[1];
    float*       out    = (float*)d_out;

    int n = in_sizes[0] / 3;                               // 999964
    long long Pll = ((long long)out_size - 3LL * n) / 129; // 1000448
    int P = (int)Pll;
    int nper = n / 4;
    int nump = P / 4;
    int biasStep = nump - nper;                            // 121

    k_zero   <<<256, 256>>>();
    k_build  <<<(n + 255) / 256, 256>>>(coords, out, n, nper, biasStep, P);
    k_scan1  <<<NSB, 256>>>();
    k_scatter<<<(n + 255) / 256, 256>>>(coords, out, n, P);
    k_gather <<<P / 32, 256>>>(feats, out, n, P, nper, nump, biasStep);
}